// round 13
// baseline (speedup 1.0000x reference)
#include <cuda_runtime.h>
#include <math.h>

// Problem constants
#define T_   256
#define B_   256
#define D_   128
#define H_   512
#define G_   1536          // 3*H
#define KX_  129           // D+1
#define PRE_ 1280          // 10*D
#define TM1_ 255           // T-1
#define P_   3

// Static scratch (allowed: __device__ globals, allocated at module load)
__device__ float g_h[B_ * H_];                         // current hidden state (B,H)
__device__ float g_outs[(size_t)T_ * B_ * H_];         // masked outs (T,B,H)
__device__ float g_gx[B_ * G_];                        // x @ w_ih^T + b_ih
__device__ float g_gh[B_ * G_];                        // h @ w_hh^T + b_hh
__device__ float g_pre[(size_t)B_ * TM1_ * PRE_];      // sigmoid MLP1 output

// ---------------------------------------------------------------------------
__global__ void init_h_kernel(const float* __restrict__ h0) {
    int i = blockIdx.x * 256 + threadIdx.x;
    if (i < B_ * H_) g_h[i] = h0[i];
}

// ---------------------------------------------------------------------------
// Per-step GRU gate GEMM.
// Computes gx[b,j] = b_ih[j] + sum_d x[t,b,d] * w_ih[j,d]          (K=129)
//          gh[b,j] = b_hh[j] + sum_h g_h[b,h] * w_hh[j,h]          (K=512)
// Tiling: BM=32 (batch), BN=64 (gate cols), BK=8, 128 threads, 4x4 per thread.
// grid = (G/64=24, B/32=8) = 192 CTAs.
__global__ __launch_bounds__(128)
void gru_gemm_kernel(const float* __restrict__ x,
                     const float* __restrict__ w_ih,
                     const float* __restrict__ w_hh,
                     const float* __restrict__ b_ih,
                     const float* __restrict__ b_hh,
                     int t)
{
    const int BM = 32, BN = 64, BK = 8;
    __shared__ __align__(16) float As[BK][BM];
    __shared__ __align__(16) float Bs[BK][BN];

    const int bn  = blockIdx.x * BN;
    const int bm  = blockIdx.y * BM;
    const int tid = threadIdx.x;
    const int tx  = tid & 15;   // -> n (4 cols each)
    const int ty  = tid >> 4;   // -> m (4 rows each)

    const float* xt = x + (size_t)t * B_ * KX_;

    float acc[4][4];

    // ================= phase 1: x_t @ w_ih^T =================
    #pragma unroll
    for (int i = 0; i < 4; i++)
        #pragma unroll
        for (int j = 0; j < 4; j++) acc[i][j] = 0.f;

    for (int k0 = 0; k0 < KX_; k0 += BK) {
        #pragma unroll
        for (int i = tid; i < BM * BK; i += 128) {
            int m = i >> 3, k = i & 7, ka = k0 + k;
            As[k][m] = (ka < KX_) ? xt[(bm + m) * KX_ + ka] : 0.f;
        }
        #pragma unroll
        for (int i = tid; i < BN * BK; i += 128) {
            int n = i >> 3, k = i & 7, ka = k0 + k;
            Bs[k][n] = (ka < KX_) ? w_ih[(bn + n) * KX_ + ka] : 0.f;
        }
        __syncthreads();
        #pragma unroll
        for (int k = 0; k < BK; k++) {
            float4 av = *(const float4*)&As[k][ty * 4];
            float4 bv = *(const float4*)&Bs[k][tx * 4];
            float a[4] = {av.x, av.y, av.z, av.w};
            float b[4] = {bv.x, bv.y, bv.z, bv.w};
            #pragma unroll
            for (int i = 0; i < 4; i++)
                #pragma unroll
                for (int j = 0; j < 4; j++) acc[i][j] += a[i] * b[j];
        }
        __syncthreads();
    }
    #pragma unroll
    for (int i = 0; i < 4; i++) {
        int m = bm + ty * 4 + i;
        #pragma unroll
        for (int j = 0; j < 4; j++) {
            int n = bn + tx * 4 + j;
            g_gx[m * G_ + n] = acc[i][j] + b_ih[n];
        }
    }

    // ================= phase 2: h @ w_hh^T =================
    #pragma unroll
    for (int i = 0; i < 4; i++)
        #pragma unroll
        for (int j = 0; j < 4; j++) acc[i][j] = 0.f;

    for (int k0 = 0; k0 < H_; k0 += BK) {
        #pragma unroll
        for (int i = tid; i < BM * BK; i += 128) {
            int m = i >> 3, k = i & 7;
            As[k][m] = g_h[(bm + m) * H_ + k0 + k];
        }
        #pragma unroll
        for (int i = tid; i < BN * BK; i += 128) {
            int n = i >> 3, k = i & 7;
            Bs[k][n] = w_hh[(bn + n) * H_ + k0 + k];
        }
        __syncthreads();
        #pragma unroll
        for (int k = 0; k < BK; k++) {
            float4 av = *(const float4*)&As[k][ty * 4];
            float4 bv = *(const float4*)&Bs[k][tx * 4];
            float a[4] = {av.x, av.y, av.z, av.w};
            float b[4] = {bv.x, bv.y, bv.z, bv.w};
            #pragma unroll
            for (int i = 0; i < 4; i++)
                #pragma unroll
                for (int j = 0; j < 4; j++) acc[i][j] += a[i] * b[j];
        }
        __syncthreads();
    }
    #pragma unroll
    for (int i = 0; i < 4; i++) {
        int m = bm + ty * 4 + i;
        #pragma unroll
        for (int j = 0; j < 4; j++) {
            int n = bn + tx * 4 + j;
            g_gh[m * G_ + n] = acc[i][j] + b_hh[n];
        }
    }
}

// ---------------------------------------------------------------------------
// Per-step gate combine + masking. B*H = 131072 threads.
__global__ __launch_bounds__(256)
void gru_combine_kernel(const int* __restrict__ lengths, int t)
{
    int idx = blockIdx.x * 256 + threadIdx.x;   // 512 blocks
    int b  = idx >> 9;        // /512
    int hh = idx & 511;

    int base = b * G_ + hh;
    float xr = g_gx[base],            hr = g_gh[base];
    float xz = g_gx[base + H_],       hz = g_gh[base + H_];
    float xn = g_gx[base + 2 * H_],   hn = g_gh[base + 2 * H_];

    float r = 1.f / (1.f + expf(-(xr + hr)));
    float z = 1.f / (1.f + expf(-(xz + hz)));
    float n = tanhf(xn + r * hn);

    float hp   = g_h[idx];
    float hnew = (1.f - z) * n + z * hp;
    bool valid = (t < lengths[b]);

    g_h[idx] = valid ? hnew : hp;
    g_outs[(size_t)t * B_ * H_ + idx] = valid ? hnew : 0.f;
}

// ---------------------------------------------------------------------------
// MLP1: pre[m,n] = sigmoid( sum_k A[m,k]*w1[n,k] + b1[n] )
// m = b*255 + t ; A[m,k] = k<512 ? outs[t,b,k] : td(b,t)
// M=65280, N=1280, K=513. BM=64, BN=128, BK=8, 256 threads, 4x8 per thread.
__global__ __launch_bounds__(256)
void mlp1_kernel(const float* __restrict__ x,
                 const float* __restrict__ w1,
                 const float* __restrict__ b1)
{
    const int BM = 64, BN = 128, BK = 8, K = 513;
    __shared__ __align__(16) float As[BK][BM];
    __shared__ __align__(16) float Bs[BK][BN];
    __shared__ int   rowbase[BM];
    __shared__ float rowtd[BM];

    const int bn  = blockIdx.x * BN;
    const int bm  = blockIdx.y * BM;
    const int tid = threadIdx.x;
    const int tx  = tid & 15;   // -> n (8 cols each)
    const int ty  = tid >> 4;   // -> m (4 rows each)

    if (tid < BM) {
        int m = bm + tid;
        int b = m / TM1_;
        int t = m - b * TM1_;
        rowbase[tid] = t * B_ * H_ + b * H_;
        rowtd[tid]   = x[(size_t)(t + 1) * B_ * KX_ + b * KX_]
                     - x[(size_t)t       * B_ * KX_ + b * KX_];
    }
    __syncthreads();

    float acc[4][8];
    #pragma unroll
    for (int i = 0; i < 4; i++)
        #pragma unroll
        for (int j = 0; j < 8; j++) acc[i][j] = 0.f;

    for (int k0 = 0; k0 < K; k0 += BK) {
        #pragma unroll
        for (int i = tid; i < BM * BK; i += 256) {
            int m = i >> 3, k = i & 7, ka = k0 + k;
            float v;
            if (ka < 512)       v = g_outs[rowbase[m] + ka];
            else if (ka == 512) v = rowtd[m];
            else                v = 0.f;
            As[k][m] = v;
        }
        #pragma unroll
        for (int i = tid; i < BN * BK; i += 256) {
            int n = i >> 3, k = i & 7, ka = k0 + k;
            Bs[k][n] = (ka < K) ? w1[(bn + n) * K + ka] : 0.f;
        }
        __syncthreads();
        #pragma unroll
        for (int k = 0; k < BK; k++) {
            float4 av  = *(const float4*)&As[k][ty * 4];
            float4 bv0 = *(const float4*)&Bs[k][tx * 8];
            float4 bv1 = *(const float4*)&Bs[k][tx * 8 + 4];
            float a[4] = {av.x, av.y, av.z, av.w};
            float b[8] = {bv0.x, bv0.y, bv0.z, bv0.w, bv1.x, bv1.y, bv1.z, bv1.w};
            #pragma unroll
            for (int i = 0; i < 4; i++)
                #pragma unroll
                for (int j = 0; j < 8; j++) acc[i][j] += a[i] * b[j];
        }
        __syncthreads();
    }

    #pragma unroll
    for (int i = 0; i < 4; i++) {
        int m = bm + ty * 4 + i;
        #pragma unroll
        for (int j = 0; j < 8; j++) {
            int n = bn + tx * 8 + j;
            float v = acc[i][j] + b1[n];
            g_pre[(size_t)m * PRE_ + n] = 1.f / (1.f + expf(-v));
        }
    }
}

// ---------------------------------------------------------------------------
// MLP2: preds[m,n] = mask * ( sum_k pre[m,k]*w2[n,k] + b2[n] )
// M=65280, N=128, K=1280. BM=64, BN=64, BK=8, 256 threads, 4x4 per thread.
__global__ __launch_bounds__(256)
void mlp2_kernel(const float* __restrict__ w2,
                 const float* __restrict__ b2,
                 const int* __restrict__ lengths,
                 float* __restrict__ out)
{
    const int BM = 64, BN = 64, BK = 8, K = 1280;
    __shared__ __align__(16) float As[BK][BM];
    __shared__ __align__(16) float Bs[BK][BN];

    const int bn  = blockIdx.x * BN;
    const int bm  = blockIdx.y * BM;
    const int tid = threadIdx.x;
    const int tx  = tid & 15;
    const int ty  = tid >> 4;

    float acc[4][4];
    #pragma unroll
    for (int i = 0; i < 4; i++)
        #pragma unroll
        for (int j = 0; j < 4; j++) acc[i][j] = 0.f;

    for (int k0 = 0; k0 < K; k0 += BK) {
        #pragma unroll
        for (int i = tid; i < BM * BK; i += 256) {
            int m = i >> 3, k = i & 7;
            As[k][m] = g_pre[(size_t)(bm + m) * PRE_ + k0 + k];
        }
        #pragma unroll
        for (int i = tid; i < BN * BK; i += 256) {
            int n = i >> 3, k = i & 7;
            Bs[k][n] = w2[(bn + n) * K + k0 + k];
        }
        __syncthreads();
        #pragma unroll
        for (int k = 0; k < BK; k++) {
            float4 av = *(const float4*)&As[k][ty * 4];
            float4 bv = *(const float4*)&Bs[k][tx * 4];
            float a[4] = {av.x, av.y, av.z, av.w};
            float b[4] = {bv.x, bv.y, bv.z, bv.w};
            #pragma unroll
            for (int i = 0; i < 4; i++)
                #pragma unroll
                for (int j = 0; j < 4; j++) acc[i][j] += a[i] * b[j];
        }
        __syncthreads();
    }

    #pragma unroll
    for (int i = 0; i < 4; i++) {
        int m = bm + ty * 4 + i;
        int b = m / TM1_;
        int t = m - b * TM1_;
        bool valid = (t < lengths[b] - 1);
        #pragma unroll
        for (int j = 0; j < 4; j++) {
            int n = bn + tx * 4 + j;
            out[(size_t)m * D_ + n] = valid ? (acc[i][j] + b2[n]) : 0.f;
        }
    }
}

// ---------------------------------------------------------------------------
// dist_params[b,p] = exp(-(h_last[b] . wp[p] + bp[p]))  and lengths-as-float.
// One warp per batch row.
__global__ __launch_bounds__(32)
void dist_len_kernel(const float* __restrict__ wp,
                     const float* __restrict__ bp,
                     const int* __restrict__ lengths,
                     float* __restrict__ out_dist,
                     float* __restrict__ out_len)
{
    int b    = blockIdx.x;
    int lane = threadIdx.x;
    const float* h = g_h + b * H_;

    float a0 = 0.f, a1 = 0.f, a2 = 0.f;
    for (int k = lane; k < H_; k += 32) {
        float hv = h[k];
        a0 += hv * wp[k];
        a1 += hv * wp[H_ + k];
        a2 += hv * wp[2 * H_ + k];
    }
    #pragma unroll
    for (int o = 16; o > 0; o >>= 1) {
        a0 += __shfl_down_sync(0xffffffffu, a0, o);
        a1 += __shfl_down_sync(0xffffffffu, a1, o);
        a2 += __shfl_down_sync(0xffffffffu, a2, o);
    }
    if (lane == 0) {
        out_dist[b * P_ + 0] = expf(-(a0 + bp[0]));
        out_dist[b * P_ + 1] = expf(-(a1 + bp[1]));
        out_dist[b * P_ + 2] = expf(-(a2 + bp[2]));
        out_len[b] = (float)lengths[b];
    }
}

// ---------------------------------------------------------------------------
extern "C" void kernel_launch(void* const* d_in, const int* in_sizes, int n_in,
                              void* d_out, int out_size)
{
    const float* x       = (const float*)d_in[0];
    const float* h0      = (const float*)d_in[1];
    const int*   lengths = (const int*)  d_in[2];
    const float* w_ih    = (const float*)d_in[3];
    const float* w_hh    = (const float*)d_in[4];
    const float* b_ih    = (const float*)d_in[5];
    const float* b_hh    = (const float*)d_in[6];
    const float* w1      = (const float*)d_in[7];
    const float* b1      = (const float*)d_in[8];
    const float* w2      = (const float*)d_in[9];
    const float* b2      = (const float*)d_in[10];
    const float* wp      = (const float*)d_in[11];
    const float* bp      = (const float*)d_in[12];
    float* out = (float*)d_out;

    // h = h0
    init_h_kernel<<<(B_ * H_ + 255) / 256, 256>>>(h0);

    // Sequential GRU scan: one GEMM + one combine per step (graph-captured chain)
    for (int t = 0; t < T_; t++) {
        gru_gemm_kernel<<<dim3(G_ / 64, B_ / 32), 128>>>(x, w_ih, w_hh, b_ih, b_hh, t);
        gru_combine_kernel<<<(B_ * H_) / 256, 256>>>(lengths, t);
    }

    // MLP head
    mlp1_kernel<<<dim3(PRE_ / 128, (B_ * TM1_) / 64), 256>>>(x, w1, b1);
    mlp2_kernel<<<dim3(D_ / 64, (B_ * TM1_) / 64), 256>>>(w2, b2, lengths, out);

    // dist_params + lengths tail of the output
    size_t preds_elems = (size_t)B_ * TM1_ * D_;
    dist_len_kernel<<<B_, 32>>>(wp, bp, lengths,
                                out + preds_elems,
                                out + preds_elems + (size_t)B_ * P_);
}

// round 14
// speedup vs baseline: 1.0008x; 1.0008x over previous
#include <cuda_runtime.h>
#include <math.h>

// Problem constants
#define T_   256
#define B_   256
#define D_   128
#define H_   512
#define G_   1536          // 3*H
#define KX_  129           // D+1
#define PRE_ 1280          // 10*D
#define TM1_ 255           // T-1
#define P_   3

// Static scratch (allowed: __device__ globals, allocated at module load)
__device__ float g_h[B_ * H_];                         // current hidden state (B,H)
__device__ float g_outs[(size_t)T_ * B_ * H_];         // masked outs (T,B,H)
__device__ float g_gx[B_ * G_];                        // x @ w_ih^T + b_ih
__device__ float g_gh[B_ * G_];                        // h @ w_hh^T + b_hh
__device__ float g_pre[(size_t)B_ * TM1_ * PRE_];      // sigmoid MLP1 output

// ---------------------------------------------------------------------------
__global__ void init_h_kernel(const float* __restrict__ h0) {
    int i = blockIdx.x * 256 + threadIdx.x;
    if (i < B_ * H_) g_h[i] = h0[i];
}

// ---------------------------------------------------------------------------
// Per-step GRU gate GEMM.
// Computes gx[b,j] = b_ih[j] + sum_d x[t,b,d] * w_ih[j,d]          (K=129)
//          gh[b,j] = b_hh[j] + sum_h g_h[b,h] * w_hh[j,h]          (K=512)
// Tiling: BM=32 (batch), BN=64 (gate cols), BK=8, 128 threads, 4x4 per thread.
// grid = (G/64=24, B/32=8) = 192 CTAs.
__global__ __launch_bounds__(128)
void gru_gemm_kernel(const float* __restrict__ x,
                     const float* __restrict__ w_ih,
                     const float* __restrict__ w_hh,
                     const float* __restrict__ b_ih,
                     const float* __restrict__ b_hh,
                     int t)
{
    const int BM = 32, BN = 64, BK = 8;
    __shared__ __align__(16) float As[BK][BM];
    __shared__ __align__(16) float Bs[BK][BN];

    const int bn  = blockIdx.x * BN;
    const int bm  = blockIdx.y * BM;
    const int tid = threadIdx.x;
    const int tx  = tid & 15;   // -> n (4 cols each)
    const int ty  = tid >> 4;   // -> m (4 rows each)

    const float* xt = x + (size_t)t * B_ * KX_;

    float acc[4][4];

    // ================= phase 1: x_t @ w_ih^T =================
    #pragma unroll
    for (int i = 0; i < 4; i++)
        #pragma unroll
        for (int j = 0; j < 4; j++) acc[i][j] = 0.f;

    for (int k0 = 0; k0 < KX_; k0 += BK) {
        #pragma unroll
        for (int i = tid; i < BM * BK; i += 128) {
            int m = i >> 3, k = i & 7, ka = k0 + k;
            As[k][m] = (ka < KX_) ? xt[(bm + m) * KX_ + ka] : 0.f;
        }
        #pragma unroll
        for (int i = tid; i < BN * BK; i += 128) {
            int n = i >> 3, k = i & 7, ka = k0 + k;
            Bs[k][n] = (ka < KX_) ? w_ih[(bn + n) * KX_ + ka] : 0.f;
        }
        __syncthreads();
        #pragma unroll
        for (int k = 0; k < BK; k++) {
            float4 av = *(const float4*)&As[k][ty * 4];
            float4 bv = *(const float4*)&Bs[k][tx * 4];
            float a[4] = {av.x, av.y, av.z, av.w};
            float b[4] = {bv.x, bv.y, bv.z, bv.w};
            #pragma unroll
            for (int i = 0; i < 4; i++)
                #pragma unroll
                for (int j = 0; j < 4; j++) acc[i][j] += a[i] * b[j];
        }
        __syncthreads();
    }
    #pragma unroll
    for (int i = 0; i < 4; i++) {
        int m = bm + ty * 4 + i;
        #pragma unroll
        for (int j = 0; j < 4; j++) {
            int n = bn + tx * 4 + j;
            g_gx[m * G_ + n] = acc[i][j] + b_ih[n];
        }
    }

    // ================= phase 2: h @ w_hh^T =================
    #pragma unroll
    for (int i = 0; i < 4; i++)
        #pragma unroll
        for (int j = 0; j < 4; j++) acc[i][j] = 0.f;

    for (int k0 = 0; k0 < H_; k0 += BK) {
        #pragma unroll
        for (int i = tid; i < BM * BK; i += 128) {
            int m = i >> 3, k = i & 7;
            As[k][m] = g_h[(bm + m) * H_ + k0 + k];
        }
        #pragma unroll
        for (int i = tid; i < BN * BK; i += 128) {
            int n = i >> 3, k = i & 7;
            Bs[k][n] = w_hh[(bn + n) * H_ + k0 + k];
        }
        __syncthreads();
        #pragma unroll
        for (int k = 0; k < BK; k++) {
            float4 av = *(const float4*)&As[k][ty * 4];
            float4 bv = *(const float4*)&Bs[k][tx * 4];
            float a[4] = {av.x, av.y, av.z, av.w};
            float b[4] = {bv.x, bv.y, bv.z, bv.w};
            #pragma unroll
            for (int i = 0; i < 4; i++)
                #pragma unroll
                for (int j = 0; j < 4; j++) acc[i][j] += a[i] * b[j];
        }
        __syncthreads();
    }
    #pragma unroll
    for (int i = 0; i < 4; i++) {
        int m = bm + ty * 4 + i;
        #pragma unroll
        for (int j = 0; j < 4; j++) {
            int n = bn + tx * 4 + j;
            g_gh[m * G_ + n] = acc[i][j] + b_hh[n];
        }
    }
}

// ---------------------------------------------------------------------------
// Per-step gate combine + masking. B*H = 131072 threads.
__global__ __launch_bounds__(256)
void gru_combine_kernel(const int* __restrict__ lengths, int t)
{
    int idx = blockIdx.x * 256 + threadIdx.x;   // 512 blocks
    int b  = idx >> 9;        // /512
    int hh = idx & 511;

    int base = b * G_ + hh;
    float xr = g_gx[base],            hr = g_gh[base];
    float xz = g_gx[base + H_],       hz = g_gh[base + H_];
    float xn = g_gx[base + 2 * H_],   hn = g_gh[base + 2 * H_];

    float r = 1.f / (1.f + expf(-(xr + hr)));
    float z = 1.f / (1.f + expf(-(xz + hz)));
    float n = tanhf(xn + r * hn);

    float hp   = g_h[idx];
    float hnew = (1.f - z) * n + z * hp;
    bool valid = (t < lengths[b]);

    g_h[idx] = valid ? hnew : hp;
    g_outs[(size_t)t * B_ * H_ + idx] = valid ? hnew : 0.f;
}

// ---------------------------------------------------------------------------
// MLP1: pre[m,n] = sigmoid( sum_k A[m,k]*w1[n,k] + b1[n] )
// m = b*255 + t ; A[m,k] = k<512 ? outs[t,b,k] : td(b,t)
// M=65280, N=1280, K=513. BM=64, BN=128, BK=8, 256 threads, 4x8 per thread.
__global__ __launch_bounds__(256)
void mlp1_kernel(const float* __restrict__ x,
                 const float* __restrict__ w1,
                 const float* __restrict__ b1)
{
    const int BM = 64, BN = 128, BK = 8, K = 513;
    __shared__ __align__(16) float As[BK][BM];
    __shared__ __align__(16) float Bs[BK][BN];
    __shared__ int   rowbase[BM];
    __shared__ float rowtd[BM];

    const int bn  = blockIdx.x * BN;
    const int bm  = blockIdx.y * BM;
    const int tid = threadIdx.x;
    const int tx  = tid & 15;   // -> n (8 cols each)
    const int ty  = tid >> 4;   // -> m (4 rows each)

    if (tid < BM) {
        int m = bm + tid;
        int b = m / TM1_;
        int t = m - b * TM1_;
        rowbase[tid] = t * B_ * H_ + b * H_;
        rowtd[tid]   = x[(size_t)(t + 1) * B_ * KX_ + b * KX_]
                     - x[(size_t)t       * B_ * KX_ + b * KX_];
    }
    __syncthreads();

    float acc[4][8];
    #pragma unroll
    for (int i = 0; i < 4; i++)
        #pragma unroll
        for (int j = 0; j < 8; j++) acc[i][j] = 0.f;

    for (int k0 = 0; k0 < K; k0 += BK) {
        #pragma unroll
        for (int i = tid; i < BM * BK; i += 256) {
            int m = i >> 3, k = i & 7, ka = k0 + k;
            float v;
            if (ka < 512)       v = g_outs[rowbase[m] + ka];
            else if (ka == 512) v = rowtd[m];
            else                v = 0.f;
            As[k][m] = v;
        }
        #pragma unroll
        for (int i = tid; i < BN * BK; i += 256) {
            int n = i >> 3, k = i & 7, ka = k0 + k;
            Bs[k][n] = (ka < K) ? w1[(bn + n) * K + ka] : 0.f;
        }
        __syncthreads();
        #pragma unroll
        for (int k = 0; k < BK; k++) {
            float4 av  = *(const float4*)&As[k][ty * 4];
            float4 bv0 = *(const float4*)&Bs[k][tx * 8];
            float4 bv1 = *(const float4*)&Bs[k][tx * 8 + 4];
            float a[4] = {av.x, av.y, av.z, av.w};
            float b[8] = {bv0.x, bv0.y, bv0.z, bv0.w, bv1.x, bv1.y, bv1.z, bv1.w};
            #pragma unroll
            for (int i = 0; i < 4; i++)
                #pragma unroll
                for (int j = 0; j < 8; j++) acc[i][j] += a[i] * b[j];
        }
        __syncthreads();
    }

    #pragma unroll
    for (int i = 0; i < 4; i++) {
        int m = bm + ty * 4 + i;
        #pragma unroll
        for (int j = 0; j < 8; j++) {
            int n = bn + tx * 8 + j;
            float v = acc[i][j] + b1[n];
            g_pre[(size_t)m * PRE_ + n] = 1.f / (1.f + expf(-v));
        }
    }
}

// ---------------------------------------------------------------------------
// MLP2: preds[m,n] = mask * ( sum_k pre[m,k]*w2[n,k] + b2[n] )
// M=65280, N=128, K=1280. BM=64, BN=64, BK=8, 256 threads, 4x4 per thread.
__global__ __launch_bounds__(256)
void mlp2_kernel(const float* __restrict__ w2,
                 const float* __restrict__ b2,
                 const int* __restrict__ lengths,
                 float* __restrict__ out)
{
    const int BM = 64, BN = 64, BK = 8, K = 1280;
    __shared__ __align__(16) float As[BK][BM];
    __shared__ __align__(16) float Bs[BK][BN];

    const int bn  = blockIdx.x * BN;
    const int bm  = blockIdx.y * BM;
    const int tid = threadIdx.x;
    const int tx  = tid & 15;
    const int ty  = tid >> 4;

    float acc[4][4];
    #pragma unroll
    for (int i = 0; i < 4; i++)
        #pragma unroll
        for (int j = 0; j < 4; j++) acc[i][j] = 0.f;

    for (int k0 = 0; k0 < K; k0 += BK) {
        #pragma unroll
        for (int i = tid; i < BM * BK; i += 256) {
            int m = i >> 3, k = i & 7;
            As[k][m] = g_pre[(size_t)(bm + m) * PRE_ + k0 + k];
        }
        #pragma unroll
        for (int i = tid; i < BN * BK; i += 256) {
            int n = i >> 3, k = i & 7;
            Bs[k][n] = w2[(bn + n) * K + k0 + k];
        }
        __syncthreads();
        #pragma unroll
        for (int k = 0; k < BK; k++) {
            float4 av = *(const float4*)&As[k][ty * 4];
            float4 bv = *(const float4*)&Bs[k][tx * 4];
            float a[4] = {av.x, av.y, av.z, av.w};
            float b[4] = {bv.x, bv.y, bv.z, bv.w};
            #pragma unroll
            for (int i = 0; i < 4; i++)
                #pragma unroll
                for (int j = 0; j < 4; j++) acc[i][j] += a[i] * b[j];
        }
        __syncthreads();
    }

    #pragma unroll
    for (int i = 0; i < 4; i++) {
        int m = bm + ty * 4 + i;
        int b = m / TM1_;
        int t = m - b * TM1_;
        bool valid = (t < lengths[b] - 1);
        #pragma unroll
        for (int j = 0; j < 4; j++) {
            int n = bn + tx * 4 + j;
            out[(size_t)m * D_ + n] = valid ? (acc[i][j] + b2[n]) : 0.f;
        }
    }
}

// ---------------------------------------------------------------------------
// dist_params[b,p] = exp(-(h_last[b] . wp[p] + bp[p]))  and lengths-as-float.
// One warp per batch row.
__global__ __launch_bounds__(32)
void dist_len_kernel(const float* __restrict__ wp,
                     const float* __restrict__ bp,
                     const int* __restrict__ lengths,
                     float* __restrict__ out_dist,
                     float* __restrict__ out_len)
{
    int b    = blockIdx.x;
    int lane = threadIdx.x;
    const float* h = g_h + b * H_;

    float a0 = 0.f, a1 = 0.f, a2 = 0.f;
    for (int k = lane; k < H_; k += 32) {
        float hv = h[k];
        a0 += hv * wp[k];
        a1 += hv * wp[H_ + k];
        a2 += hv * wp[2 * H_ + k];
    }
    #pragma unroll
    for (int o = 16; o > 0; o >>= 1) {
        a0 += __shfl_down_sync(0xffffffffu, a0, o);
        a1 += __shfl_down_sync(0xffffffffu, a1, o);
        a2 += __shfl_down_sync(0xffffffffu, a2, o);
    }
    if (lane == 0) {
        out_dist[b * P_ + 0] = expf(-(a0 + bp[0]));
        out_dist[b * P_ + 1] = expf(-(a1 + bp[1]));
        out_dist[b * P_ + 2] = expf(-(a2 + bp[2]));
        out_len[b] = (float)lengths[b];
    }
}

// ---------------------------------------------------------------------------
extern "C" void kernel_launch(void* const* d_in, const int* in_sizes, int n_in,
                              void* d_out, int out_size)
{
    const float* x       = (const float*)d_in[0];
    const float* h0      = (const float*)d_in[1];
    const int*   lengths = (const int*)  d_in[2];
    const float* w_ih    = (const float*)d_in[3];
    const float* w_hh    = (const float*)d_in[4];
    const float* b_ih    = (const float*)d_in[5];
    const float* b_hh    = (const float*)d_in[6];
    const float* w1      = (const float*)d_in[7];
    const float* b1      = (const float*)d_in[8];
    const float* w2      = (const float*)d_in[9];
    const float* b2      = (const float*)d_in[10];
    const float* wp      = (const float*)d_in[11];
    const float* bp      = (const float*)d_in[12];
    float* out = (float*)d_out;

    // h = h0
    init_h_kernel<<<(B_ * H_ + 255) / 256, 256>>>(h0);

    // Sequential GRU scan: one GEMM + one combine per step (graph-captured chain)
    for (int t = 0; t < T_; t++) {
        gru_gemm_kernel<<<dim3(G_ / 64, B_ / 32), 128>>>(x, w_ih, w_hh, b_ih, b_hh, t);
        gru_combine_kernel<<<(B_ * H_) / 256, 256>>>(lengths, t);
    }

    // MLP head
    mlp1_kernel<<<dim3(PRE_ / 128, (B_ * TM1_) / 64), 256>>>(x, w1, b1);
    mlp2_kernel<<<dim3(D_ / 64, (B_ * TM1_) / 64), 256>>>(w2, b2, lengths, out);

    // dist_params + lengths tail of the output
    size_t preds_elems = (size_t)B_ * TM1_ * D_;
    dist_len_kernel<<<B_, 32>>>(wp, bp, lengths,
                                out + preds_elems,
                                out + preds_elems + (size_t)B_ * P_);
}

// round 15
// speedup vs baseline: 1.0025x; 1.0017x over previous
#include <cuda_runtime.h>
#include <math.h>

// Problem constants
#define T_   256
#define B_   256
#define D_   128
#define H_   512
#define G_   1536          // 3*H
#define KX_  129           // D+1
#define PRE_ 1280          // 10*D
#define TM1_ 255           // T-1
#define P_   3

// Static scratch (allowed: __device__ globals, allocated at module load)
__device__ float g_h[B_ * H_];                         // current hidden state (B,H)
__device__ float g_outs[(size_t)T_ * B_ * H_];         // masked outs (T,B,H)
__device__ float g_gx[B_ * G_];                        // x @ w_ih^T + b_ih
__device__ float g_gh[B_ * G_];                        // h @ w_hh^T + b_hh
__device__ float g_pre[(size_t)B_ * TM1_ * PRE_];      // sigmoid MLP1 output

// ---------------------------------------------------------------------------
__global__ void init_h_kernel(const float* __restrict__ h0) {
    int i = blockIdx.x * 256 + threadIdx.x;
    if (i < B_ * H_) g_h[i] = h0[i];
}

// ---------------------------------------------------------------------------
// Per-step GRU gate GEMM.
// Computes gx[b,j] = b_ih[j] + sum_d x[t,b,d] * w_ih[j,d]          (K=129)
//          gh[b,j] = b_hh[j] + sum_h g_h[b,h] * w_hh[j,h]          (K=512)
// Tiling: BM=32 (batch), BN=64 (gate cols), BK=8, 128 threads, 4x4 per thread.
// grid = (G/64=24, B/32=8) = 192 CTAs.
__global__ __launch_bounds__(128)
void gru_gemm_kernel(const float* __restrict__ x,
                     const float* __restrict__ w_ih,
                     const float* __restrict__ w_hh,
                     const float* __restrict__ b_ih,
                     const float* __restrict__ b_hh,
                     int t)
{
    const int BM = 32, BN = 64, BK = 8;
    __shared__ __align__(16) float As[BK][BM];
    __shared__ __align__(16) float Bs[BK][BN];

    const int bn  = blockIdx.x * BN;
    const int bm  = blockIdx.y * BM;
    const int tid = threadIdx.x;
    const int tx  = tid & 15;   // -> n (4 cols each)
    const int ty  = tid >> 4;   // -> m (4 rows each)

    const float* xt = x + (size_t)t * B_ * KX_;

    float acc[4][4];

    // ================= phase 1: x_t @ w_ih^T =================
    #pragma unroll
    for (int i = 0; i < 4; i++)
        #pragma unroll
        for (int j = 0; j < 4; j++) acc[i][j] = 0.f;

    for (int k0 = 0; k0 < KX_; k0 += BK) {
        #pragma unroll
        for (int i = tid; i < BM * BK; i += 128) {
            int m = i >> 3, k = i & 7, ka = k0 + k;
            As[k][m] = (ka < KX_) ? xt[(bm + m) * KX_ + ka] : 0.f;
        }
        #pragma unroll
        for (int i = tid; i < BN * BK; i += 128) {
            int n = i >> 3, k = i & 7, ka = k0 + k;
            Bs[k][n] = (ka < KX_) ? w_ih[(bn + n) * KX_ + ka] : 0.f;
        }
        __syncthreads();
        #pragma unroll
        for (int k = 0; k < BK; k++) {
            float4 av = *(const float4*)&As[k][ty * 4];
            float4 bv = *(const float4*)&Bs[k][tx * 4];
            float a[4] = {av.x, av.y, av.z, av.w};
            float b[4] = {bv.x, bv.y, bv.z, bv.w};
            #pragma unroll
            for (int i = 0; i < 4; i++)
                #pragma unroll
                for (int j = 0; j < 4; j++) acc[i][j] += a[i] * b[j];
        }
        __syncthreads();
    }
    #pragma unroll
    for (int i = 0; i < 4; i++) {
        int m = bm + ty * 4 + i;
        #pragma unroll
        for (int j = 0; j < 4; j++) {
            int n = bn + tx * 4 + j;
            g_gx[m * G_ + n] = acc[i][j] + b_ih[n];
        }
    }

    // ================= phase 2: h @ w_hh^T =================
    #pragma unroll
    for (int i = 0; i < 4; i++)
        #pragma unroll
        for (int j = 0; j < 4; j++) acc[i][j] = 0.f;

    for (int k0 = 0; k0 < H_; k0 += BK) {
        #pragma unroll
        for (int i = tid; i < BM * BK; i += 128) {
            int m = i >> 3, k = i & 7;
            As[k][m] = g_h[(bm + m) * H_ + k0 + k];
        }
        #pragma unroll
        for (int i = tid; i < BN * BK; i += 128) {
            int n = i >> 3, k = i & 7;
            Bs[k][n] = w_hh[(bn + n) * H_ + k0 + k];
        }
        __syncthreads();
        #pragma unroll
        for (int k = 0; k < BK; k++) {
            float4 av = *(const float4*)&As[k][ty * 4];
            float4 bv = *(const float4*)&Bs[k][tx * 4];
            float a[4] = {av.x, av.y, av.z, av.w};
            float b[4] = {bv.x, bv.y, bv.z, bv.w};
            #pragma unroll
            for (int i = 0; i < 4; i++)
                #pragma unroll
                for (int j = 0; j < 4; j++) acc[i][j] += a[i] * b[j];
        }
        __syncthreads();
    }
    #pragma unroll
    for (int i = 0; i < 4; i++) {
        int m = bm + ty * 4 + i;
        #pragma unroll
        for (int j = 0; j < 4; j++) {
            int n = bn + tx * 4 + j;
            g_gh[m * G_ + n] = acc[i][j] + b_hh[n];
        }
    }
}

// ---------------------------------------------------------------------------
// Per-step gate combine + masking. B*H = 131072 threads.
__global__ __launch_bounds__(256)
void gru_combine_kernel(const int* __restrict__ lengths, int t)
{
    int idx = blockIdx.x * 256 + threadIdx.x;   // 512 blocks
    int b  = idx >> 9;        // /512
    int hh = idx & 511;

    int base = b * G_ + hh;
    float xr = g_gx[base],            hr = g_gh[base];
    float xz = g_gx[base + H_],       hz = g_gh[base + H_];
    float xn = g_gx[base + 2 * H_],   hn = g_gh[base + 2 * H_];

    float r = 1.f / (1.f + expf(-(xr + hr)));
    float z = 1.f / (1.f + expf(-(xz + hz)));
    float n = tanhf(xn + r * hn);

    float hp   = g_h[idx];
    float hnew = (1.f - z) * n + z * hp;
    bool valid = (t < lengths[b]);

    g_h[idx] = valid ? hnew : hp;
    g_outs[(size_t)t * B_ * H_ + idx] = valid ? hnew : 0.f;
}

// ---------------------------------------------------------------------------
// MLP1: pre[m,n] = sigmoid( sum_k A[m,k]*w1[n,k] + b1[n] )
// m = b*255 + t ; A[m,k] = k<512 ? outs[t,b,k] : td(b,t)
// M=65280, N=1280, K=513. BM=64, BN=128, BK=8, 256 threads, 4x8 per thread.
__global__ __launch_bounds__(256)
void mlp1_kernel(const float* __restrict__ x,
                 const float* __restrict__ w1,
                 const float* __restrict__ b1)
{
    const int BM = 64, BN = 128, BK = 8, K = 513;
    __shared__ __align__(16) float As[BK][BM];
    __shared__ __align__(16) float Bs[BK][BN];
    __shared__ int   rowbase[BM];
    __shared__ float rowtd[BM];

    const int bn  = blockIdx.x * BN;
    const int bm  = blockIdx.y * BM;
    const int tid = threadIdx.x;
    const int tx  = tid & 15;   // -> n (8 cols each)
    const int ty  = tid >> 4;   // -> m (4 rows each)

    if (tid < BM) {
        int m = bm + tid;
        int b = m / TM1_;
        int t = m - b * TM1_;
        rowbase[tid] = t * B_ * H_ + b * H_;
        rowtd[tid]   = x[(size_t)(t + 1) * B_ * KX_ + b * KX_]
                     - x[(size_t)t       * B_ * KX_ + b * KX_];
    }
    __syncthreads();

    float acc[4][8];
    #pragma unroll
    for (int i = 0; i < 4; i++)
        #pragma unroll
        for (int j = 0; j < 8; j++) acc[i][j] = 0.f;

    for (int k0 = 0; k0 < K; k0 += BK) {
        #pragma unroll
        for (int i = tid; i < BM * BK; i += 256) {
            int m = i >> 3, k = i & 7, ka = k0 + k;
            float v;
            if (ka < 512)       v = g_outs[rowbase[m] + ka];
            else if (ka == 512) v = rowtd[m];
            else                v = 0.f;
            As[k][m] = v;
        }
        #pragma unroll
        for (int i = tid; i < BN * BK; i += 256) {
            int n = i >> 3, k = i & 7, ka = k0 + k;
            Bs[k][n] = (ka < K) ? w1[(bn + n) * K + ka] : 0.f;
        }
        __syncthreads();
        #pragma unroll
        for (int k = 0; k < BK; k++) {
            float4 av  = *(const float4*)&As[k][ty * 4];
            float4 bv0 = *(const float4*)&Bs[k][tx * 8];
            float4 bv1 = *(const float4*)&Bs[k][tx * 8 + 4];
            float a[4] = {av.x, av.y, av.z, av.w};
            float b[8] = {bv0.x, bv0.y, bv0.z, bv0.w, bv1.x, bv1.y, bv1.z, bv1.w};
            #pragma unroll
            for (int i = 0; i < 4; i++)
                #pragma unroll
                for (int j = 0; j < 8; j++) acc[i][j] += a[i] * b[j];
        }
        __syncthreads();
    }

    #pragma unroll
    for (int i = 0; i < 4; i++) {
        int m = bm + ty * 4 + i;
        #pragma unroll
        for (int j = 0; j < 8; j++) {
            int n = bn + tx * 8 + j;
            float v = acc[i][j] + b1[n];
            g_pre[(size_t)m * PRE_ + n] = 1.f / (1.f + expf(-v));
        }
    }
}

// ---------------------------------------------------------------------------
// MLP2: preds[m,n] = mask * ( sum_k pre[m,k]*w2[n,k] + b2[n] )
// M=65280, N=128, K=1280. BM=64, BN=64, BK=8, 256 threads, 4x4 per thread.
__global__ __launch_bounds__(256)
void mlp2_kernel(const float* __restrict__ w2,
                 const float* __restrict__ b2,
                 const int* __restrict__ lengths,
                 float* __restrict__ out)
{
    const int BM = 64, BN = 64, BK = 8, K = 1280;
    __shared__ __align__(16) float As[BK][BM];
    __shared__ __align__(16) float Bs[BK][BN];

    const int bn  = blockIdx.x * BN;
    const int bm  = blockIdx.y * BM;
    const int tid = threadIdx.x;
    const int tx  = tid & 15;
    const int ty  = tid >> 4;

    float acc[4][4];
    #pragma unroll
    for (int i = 0; i < 4; i++)
        #pragma unroll
        for (int j = 0; j < 4; j++) acc[i][j] = 0.f;

    for (int k0 = 0; k0 < K; k0 += BK) {
        #pragma unroll
        for (int i = tid; i < BM * BK; i += 256) {
            int m = i >> 3, k = i & 7;
            As[k][m] = g_pre[(size_t)(bm + m) * PRE_ + k0 + k];
        }
        #pragma unroll
        for (int i = tid; i < BN * BK; i += 256) {
            int n = i >> 3, k = i & 7;
            Bs[k][n] = w2[(bn + n) * K + k0 + k];
        }
        __syncthreads();
        #pragma unroll
        for (int k = 0; k < BK; k++) {
            float4 av = *(const float4*)&As[k][ty * 4];
            float4 bv = *(const float4*)&Bs[k][tx * 4];
            float a[4] = {av.x, av.y, av.z, av.w};
            float b[4] = {bv.x, bv.y, bv.z, bv.w};
            #pragma unroll
            for (int i = 0; i < 4; i++)
                #pragma unroll
                for (int j = 0; j < 4; j++) acc[i][j] += a[i] * b[j];
        }
        __syncthreads();
    }

    #pragma unroll
    for (int i = 0; i < 4; i++) {
        int m = bm + ty * 4 + i;
        int b = m / TM1_;
        int t = m - b * TM1_;
        bool valid = (t < lengths[b] - 1);
        #pragma unroll
        for (int j = 0; j < 4; j++) {
            int n = bn + tx * 4 + j;
            out[(size_t)m * D_ + n] = valid ? (acc[i][j] + b2[n]) : 0.f;
        }
    }
}

// ---------------------------------------------------------------------------
// dist_params[b,p] = exp(-(h_last[b] . wp[p] + bp[p]))  and lengths-as-float.
// One warp per batch row.
__global__ __launch_bounds__(32)
void dist_len_kernel(const float* __restrict__ wp,
                     const float* __restrict__ bp,
                     const int* __restrict__ lengths,
                     float* __restrict__ out_dist,
                     float* __restrict__ out_len)
{
    int b    = blockIdx.x;
    int lane = threadIdx.x;
    const float* h = g_h + b * H_;

    float a0 = 0.f, a1 = 0.f, a2 = 0.f;
    for (int k = lane; k < H_; k += 32) {
        float hv = h[k];
        a0 += hv * wp[k];
        a1 += hv * wp[H_ + k];
        a2 += hv * wp[2 * H_ + k];
    }
    #pragma unroll
    for (int o = 16; o > 0; o >>= 1) {
        a0 += __shfl_down_sync(0xffffffffu, a0, o);
        a1 += __shfl_down_sync(0xffffffffu, a1, o);
        a2 += __shfl_down_sync(0xffffffffu, a2, o);
    }
    if (lane == 0) {
        out_dist[b * P_ + 0] = expf(-(a0 + bp[0]));
        out_dist[b * P_ + 1] = expf(-(a1 + bp[1]));
        out_dist[b * P_ + 2] = expf(-(a2 + bp[2]));
        out_len[b] = (float)lengths[b];
    }
}

// ---------------------------------------------------------------------------
extern "C" void kernel_launch(void* const* d_in, const int* in_sizes, int n_in,
                              void* d_out, int out_size)
{
    const float* x       = (const float*)d_in[0];
    const float* h0      = (const float*)d_in[1];
    const int*   lengths = (const int*)  d_in[2];
    const float* w_ih    = (const float*)d_in[3];
    const float* w_hh    = (const float*)d_in[4];
    const float* b_ih    = (const float*)d_in[5];
    const float* b_hh    = (const float*)d_in[6];
    const float* w1      = (const float*)d_in[7];
    const float* b1      = (const float*)d_in[8];
    const float* w2      = (const float*)d_in[9];
    const float* b2      = (const float*)d_in[10];
    const float* wp      = (const float*)d_in[11];
    const float* bp      = (const float*)d_in[12];
    float* out = (float*)d_out;

    // h = h0
    init_h_kernel<<<(B_ * H_ + 255) / 256, 256>>>(h0);

    // Sequential GRU scan: one GEMM + one combine per step (graph-captured chain)
    for (int t = 0; t < T_; t++) {
        gru_gemm_kernel<<<dim3(G_ / 64, B_ / 32), 128>>>(x, w_ih, w_hh, b_ih, b_hh, t);
        gru_combine_kernel<<<(B_ * H_) / 256, 256>>>(lengths, t);
    }

    // MLP head
    mlp1_kernel<<<dim3(PRE_ / 128, (B_ * TM1_) / 64), 256>>>(x, w1, b1);
    mlp2_kernel<<<dim3(D_ / 64, (B_ * TM1_) / 64), 256>>>(w2, b2, lengths, out);

    // dist_params + lengths tail of the output
    size_t preds_elems = (size_t)B_ * TM1_ * D_;
    dist_len_kernel<<<B_, 32>>>(wp, bp, lengths,
                                out + preds_elems,
                                out + preds_elems + (size_t)B_ * P_);
}